// round 16
// baseline (speedup 1.0000x reference)
#include <cuda_runtime.h>
#include <cuda_fp16.h>
#include <cstdint>

#define NN 32
#define CC 64
#define TT 512
#define VV 25
#define HH 3
#define TB 8
#define TOTAL (NN*CC*TT*VV)     // 26214400
#define NROWS (NN*CC*TT)        // 1048576 padded rows
#define CNT_F (NN*TT*VV)        // 409600

// smem layout (bytes)
#define XS 264                  // X row stride in halves: 8*32 + 8 pad
#define XH_B 0                  // half [64][264]   = 33792 B
#define AH_B 33792              // half [96][40]    = 7680 B
#define ST_B 41472              // float [128]      = 512 B
#define SM_BYTES 41984

__device__ __half2 g_convP[NROWS*16];   // conv out fp16, rows padded to 32 halves (64B)
__device__ uint4   g_Wf[HH*4*4*32];     // per-lane W a-fragments, LDG.128-ready
__device__ float   g_stats[128];
__device__ float   g_scale[CC];
__device__ float   g_shift[CC];

__device__ __forceinline__ uint32_t smem_u32(const void* p) {
    uint32_t a;
    asm("{ .reg .u64 t; cvta.to.shared.u64 t, %1; cvt.u32.u64 %0, t; }" : "=r"(a) : "l"(p));
    return a;
}
__device__ __forceinline__ void ldmx4t(uint32_t& r0, uint32_t& r1, uint32_t& r2, uint32_t& r3, uint32_t a) {
    asm volatile("ldmatrix.sync.aligned.m8n8.x4.trans.shared.b16 {%0,%1,%2,%3},[%4];"
                 : "=r"(r0), "=r"(r1), "=r"(r2), "=r"(r3) : "r"(a));
}
__device__ __forceinline__ void ldmx2(uint32_t& r0, uint32_t& r1, uint32_t a) {
    asm volatile("ldmatrix.sync.aligned.m8n8.x2.shared.b16 {%0,%1},[%2];"
                 : "=r"(r0), "=r"(r1) : "r"(a));
}
__device__ __forceinline__ void mma16(float* c, const uint32_t* a, uint32_t b0, uint32_t b1) {
    asm volatile("mma.sync.aligned.m16n8k16.row.col.f32.f16.f16.f32 "
        "{%0,%1,%2,%3},{%4,%5,%6,%7},{%8,%9},{%0,%1,%2,%3};"
        : "+f"(c[0]), "+f"(c[1]), "+f"(c[2]), "+f"(c[3])
        : "r"(a[0]), "r"(a[1]), "r"(a[2]), "r"(a[3]), "r"(b0), "r"(b1));
}
__device__ __forceinline__ uint32_t h2u(__half2 h) { return *reinterpret_cast<uint32_t*>(&h); }

// ---------------------------------------------------------------------------
// prep: bake W into per-lane mma a-fragment order, zero stats.
// ---------------------------------------------------------------------------
__global__ void prep_k(const float* __restrict__ W) {
    int i = blockIdx.x * blockDim.x + threadIdx.x;
    if (i < HH*4*4*32*4) {
        int r    = i & 3;
        int lane = (i >> 2) & 31;
        int kk   = (i >> 7) & 3;
        int w4   = (i >> 9) & 3;
        int h    = i >> 11;
        int grp = lane >> 2, tig = lane & 3;
        int o = w4*16 + grp + (r & 1)*8;
        int c = kk*16 + ((r & 2) ? 8 : 0) + tig*2;
        const float* wp = W + (h*CC + o)*CC + c;
        reinterpret_cast<uint32_t*>(g_Wf)[i] = h2u(__floats2half2_rn(wp[0], wp[1]));
    }
    if (i < 128) g_stats[i] = 0.f;
}

// ---------------------------------------------------------------------------
// conv: fp16 mma.m16n8k16, fp32 accum. CTA = (n, 8 t's), 128 thr, 5 CTAs/SM.
// Same as R15 except X b-fragments loaded per (h,kk) (8 live regs, not 32)
// to fit 5 CTAs/SM in the register file.
// ---------------------------------------------------------------------------
__global__ __launch_bounds__(128, 5) void conv_mma(const float* __restrict__ x,
                                                   const float* __restrict__ A) {
    extern __shared__ char sm[];
    __half* Xh = (__half*)(sm + XH_B);
    __half* Ah = (__half*)(sm + AH_B);
    float*  St = (float*)(sm + ST_B);

    const uint32_t smb = smem_u32(sm);
    const int tid  = threadIdx.x;
    const int warp = tid >> 5, lane = tid & 31;
    const int grp  = lane >> 2, tig = lane & 3;
    const int n    = blockIdx.x >> 6;            // 64 t-blocks per n
    const int t0   = (blockIdx.x & 63) * TB;

    St[tid] = 0.f;

    // --- A smem: [3*32][40] halves, zero-padded beyond 25x25 ---
    for (int i = tid; i < HH*32*32; i += 128) {
        int h = i >> 10, rem = i & 1023;
        int v = rem >> 5, u = rem & 31;
        float val = (v < VV && u < VV) ? A[(h*VV + v)*VV + u] : 0.f;
        Ah[(h*32 + v)*40 + u] = __float2half_rn(val);
    }
    // --- X pad: cols 32t+25..32t+31 zero, all 64 rows ---
    for (int i = tid; i < 64*56; i += 128) {
        int r = i / 56, k = i - r*56;
        int col = 32*(k/7) + 25 + (k%7);
        Xh[r*XS + col] = __float2half(0.f);
    }
    // --- X fill natural: Xh[c][32*(s/25) + s%25] from 200 contiguous floats/c ---
    {
        const float4* x4 = reinterpret_cast<const float4*>(x);
        for (int i = tid; i < CC*50; i += 128) {
            int c = i / 50, q = i - c*50;
            unsigned base = ((unsigned)(n*CC + c)*TT + t0)*VV;   // divisible by 4
            float4 v = x4[(base >> 2) + q];
            float vv[4] = {v.x, v.y, v.z, v.w};
            #pragma unroll
            for (int e = 0; e < 4; ++e) {
                int s = q*4 + e;
                int col = (s/25)*32 + (s - (s/25)*25);
                Xh[c*XS + col] = __float2half_rn(vv[e]);
            }
        }
    }
    __syncthreads();

    // ldmatrix address components
    const int q4 = lane >> 3, r8 = lane & 7;
    const int brow = lane & 7;
    const int bcol8 = (lane & 8) ? 8 : 0;
    const uint32_t xlane = (uint32_t)((r8 + ((q4 & 1) ? 8 : 0)) * XS + ((q4 & 2) ? 8 : 0)) * 2;

    const uint4* wbase = g_Wf + warp*4*32 + lane;

    float st1a = 0.f, st2a = 0.f, st1b = 0.f, st2b = 0.f;
    const int r0 = warp*16 + grp, r1 = r0 + 8;

    for (int t = 0; t < TB; ++t) {
        float OUT[4][4];
        #pragma unroll
        for (int nv = 0; nv < 4; ++nv)
            #pragma unroll
            for (int e = 0; e < 4; ++e) OUT[nv][e] = 0.f;

        #pragma unroll
        for (int h = 0; h < HH; ++h) {
            // stage-2 B fragments for this head (16 regs)
            uint32_t B2[4][2][2];
            #pragma unroll
            for (int nv = 0; nv < 4; ++nv)
                #pragma unroll
                for (int kp = 0; kp < 2; ++kp) {
                    uint32_t off = (uint32_t)(((h*32 + 8*nv + brow)*40) + kp*16 + bcol8) * 2;
                    ldmx2(B2[nv][kp][0], B2[nv][kp][1], smb + AH_B + off);
                }

            // stage 1 (X fragments loaded per kk: 8 live regs)
            float Y[4][4];
            #pragma unroll
            for (int j = 0; j < 4; ++j)
                #pragma unroll
                for (int e = 0; e < 4; ++e) Y[j][e] = 0.f;

            #pragma unroll
            for (int kk = 0; kk < 4; ++kk) {
                uint4 wv = __ldg(wbase + (h*16 + kk)*32);
                uint32_t whf[4] = {wv.x, wv.y, wv.z, wv.w};
                uint32_t xk[2][4];
                #pragma unroll
                for (int jp = 0; jp < 2; ++jp) {
                    uint32_t off = xlane + (uint32_t)((16*kk)*XS + 32*t + 16*jp) * 2;
                    ldmx4t(xk[jp][0], xk[jp][1], xk[jp][2], xk[jp][3],
                           smb + XH_B + off);
                }
                #pragma unroll
                for (int j = 0; j < 4; ++j) {
                    int jp = j >> 1, ix = (j & 1) * 2;
                    mma16(Y[j], whf, xk[jp][ix], xk[jp][ix + 1]);
                }
            }

            // stage 2: in-register Y -> a-frags, accumulate OUT
            #pragma unroll
            for (int kp = 0; kp < 2; ++kp) {
                uint32_t ah[4];
                #pragma unroll
                for (int i = 0; i < 4; ++i) {
                    const float* yp = Y[2*kp + (i >> 1)];
                    float p  = yp[(i & 1) ? 2 : 0];
                    float qv = yp[(i & 1) ? 3 : 1];
                    ah[i] = h2u(__floats2half2_rn(p, qv));
                }
                #pragma unroll
                for (int nv = 0; nv < 4; ++nv)
                    mma16(OUT[nv], ah, B2[nv][kp][0], B2[nv][kp][1]);
            }
        }

        // ---- branchless epilogue: aligned half2 stores into 64B rows ----
        unsigned rowA = ((unsigned)(n*CC + r0)*TT + t0 + t);
        unsigned rowB = ((unsigned)(n*CC + r1)*TT + t0 + t);
        #pragma unroll
        for (int nv = 0; nv < 4; ++nv) {
            int p2 = (8*nv + 2*tig) >> 1;       // half2 slot within row
            float a0 = OUT[nv][0], a1 = OUT[nv][1];
            float b0 = OUT[nv][2], b1 = OUT[nv][3];
            g_convP[rowA*16 + p2] = __floats2half2_rn(a0, a1);
            g_convP[rowB*16 + p2] = __floats2half2_rn(b0, b1);
            st1a += a0 + a1; st2a += a0*a0 + a1*a1;
            st1b += b0 + b1; st2b += b0*b0 + b1*b1;
        }
    }

    // --- stats: smem reduce, one global atomic per tid ---
    atomicAdd(&St[r0],      st1a);
    atomicAdd(&St[64 + r0], st2a);
    atomicAdd(&St[r1],      st1b);
    atomicAdd(&St[64 + r1], st2b);
    __syncthreads();
    atomicAdd(&g_stats[tid], St[tid]);
}

// ---------------------------------------------------------------------------
__global__ void stats_k(const float* __restrict__ gamma, const float* __restrict__ beta) {
    int o = threadIdx.x;
    if (o < CC) {
        const float inv = 1.f / (float)CNT_F;
        float mean = g_stats[o] * inv;
        float var  = g_stats[64 + o] * inv - mean*mean;
        float sc = gamma[o] * rsqrtf(var + 1e-5f);
        g_scale[o] = sc;
        g_shift[o] = beta[o] - mean*sc;
    }
}

// ---------------------------------------------------------------------------
// pass 2: out = relu(scale[c]*convP + shift[c] + x); convP rows padded to 32.
// ---------------------------------------------------------------------------
__global__ void bn_apply(const float4* __restrict__ xv, float4* __restrict__ ov) {
    const __half* ch = reinterpret_cast<const __half*>(g_convP);
    const int n4 = TOTAL / 4;
    int stride = gridDim.x * blockDim.x;
    for (int i = blockIdx.x * blockDim.x + threadIdx.x; i < n4; i += stride) {
        unsigned g = (unsigned)i * 4u;
        unsigned q = g / 25u;
        int v = (int)(g - q*25u);
        int c = (q >> 9) & 63;
        float s  = __ldg(&g_scale[c]);
        float sh = __ldg(&g_shift[c]);
        float4 b = xv[i];
        float f[4];
        #pragma unroll
        for (int e = 0; e < 4; ++e) {
            int ve = v + e;
            int w = (ve >= VV) ? 1 : 0;
            f[e] = __half2float(__ldg(ch + (q + w)*32u + (ve - VV*w)));
        }
        float4 r;
        r.x = fmaxf(fmaf(s, f[0], sh) + b.x, 0.f);
        r.y = fmaxf(fmaf(s, f[1], sh) + b.y, 0.f);
        r.z = fmaxf(fmaf(s, f[2], sh) + b.z, 0.f);
        r.w = fmaxf(fmaf(s, f[3], sh) + b.w, 0.f);
        ov[i] = r;
    }
}

// ---------------------------------------------------------------------------
extern "C" void kernel_launch(void* const* d_in, const int* in_sizes, int n_in,
                              void* d_out, int out_size) {
    const float* x     = (const float*)d_in[0];
    const float* A     = (const float*)d_in[1];
    const float* W     = (const float*)d_in[2];
    // d_in[3] = b : cancels exactly under training-mode BatchNorm -> unused
    const float* gamma = (const float*)d_in[4];
    const float* beta  = (const float*)d_in[5];
    float* out = (float*)d_out;

    cudaFuncSetAttribute(conv_mma, cudaFuncAttributeMaxDynamicSharedMemorySize, SM_BYTES);

    prep_k<<<48, 256>>>(W);
    conv_mma<<<NN*(TT/TB), 128, SM_BYTES>>>(x, A);
    stats_k<<<1, 64>>>(gamma, beta);
    bn_apply<<<4096, 256>>>(reinterpret_cast<const float4*>(x),
                            reinterpret_cast<float4*>(out));
}

// round 17
// speedup vs baseline: 1.0130x; 1.0130x over previous
#include <cuda_runtime.h>
#include <cuda_fp16.h>
#include <cstdint>

#define NN 32
#define CC 64
#define TT 512
#define VV 25
#define HH 3
#define TB 8
#define TOTAL (NN*CC*TT*VV)     // 26214400
#define NROWS (NN*CC*TT)        // 1048576 padded rows
#define CNT_F (NN*TT*VV)        // 409600

// smem layout (bytes)
#define XS 264                  // X row stride in halves: 8*32 + 8 pad
#define XH_B 0                  // half [64][264]   = 33792 B
#define AH_B 33792              // half [96][40]    = 7680 B
#define ST_B 41472              // float [128]      = 512 B
#define SM_BYTES 41984

__device__ __half2 g_convP[NROWS*16];   // conv out fp16, rows padded to 32 halves (64B)
__device__ uint4   g_Wf[HH*4*4*32];     // per-lane W a-fragments, LDG.128-ready
__device__ float   g_stats[128];
__device__ float   g_scale[CC];
__device__ float   g_shift[CC];

__device__ __forceinline__ uint32_t smem_u32(const void* p) {
    uint32_t a;
    asm("{ .reg .u64 t; cvta.to.shared.u64 t, %1; cvt.u32.u64 %0, t; }" : "=r"(a) : "l"(p));
    return a;
}
__device__ __forceinline__ void ldmx4t(uint32_t& r0, uint32_t& r1, uint32_t& r2, uint32_t& r3, uint32_t a) {
    asm volatile("ldmatrix.sync.aligned.m8n8.x4.trans.shared.b16 {%0,%1,%2,%3},[%4];"
                 : "=r"(r0), "=r"(r1), "=r"(r2), "=r"(r3) : "r"(a));
}
__device__ __forceinline__ void ldmx2(uint32_t& r0, uint32_t& r1, uint32_t a) {
    asm volatile("ldmatrix.sync.aligned.m8n8.x2.shared.b16 {%0,%1},[%2];"
                 : "=r"(r0), "=r"(r1) : "r"(a));
}
__device__ __forceinline__ void mma16(float* c, const uint32_t* a, uint32_t b0, uint32_t b1) {
    asm volatile("mma.sync.aligned.m16n8k16.row.col.f32.f16.f16.f32 "
        "{%0,%1,%2,%3},{%4,%5,%6,%7},{%8,%9},{%0,%1,%2,%3};"
        : "+f"(c[0]), "+f"(c[1]), "+f"(c[2]), "+f"(c[3])
        : "r"(a[0]), "r"(a[1]), "r"(a[2]), "r"(a[3]), "r"(b0), "r"(b1));
}
__device__ __forceinline__ uint32_t h2u(__half2 h) { return *reinterpret_cast<uint32_t*>(&h); }

// ---------------------------------------------------------------------------
// prep: bake W into per-lane mma a-fragment order, zero stats.
// ---------------------------------------------------------------------------
__global__ void prep_k(const float* __restrict__ W) {
    int i = blockIdx.x * blockDim.x + threadIdx.x;
    if (i < HH*4*4*32*4) {
        int r    = i & 3;
        int lane = (i >> 2) & 31;
        int kk   = (i >> 7) & 3;
        int w4   = (i >> 9) & 3;
        int h    = i >> 11;
        int grp = lane >> 2, tig = lane & 3;
        int o = w4*16 + grp + (r & 1)*8;
        int c = kk*16 + ((r & 2) ? 8 : 0) + tig*2;
        const float* wp = W + (h*CC + o)*CC + c;
        reinterpret_cast<uint32_t*>(g_Wf)[i] = h2u(__floats2half2_rn(wp[0], wp[1]));
    }
    if (i < 128) g_stats[i] = 0.f;
}

// ---------------------------------------------------------------------------
// conv: fp16 mma.m16n8k16, fp32 accum. CTA = (n, 8 t's), 128 thr, 5 CTAs/SM.
// R15 structure; B2 fragments loaded inside the kp loop (same LDSM count,
// lower liveness) to fit 5 CTAs/SM.
// ---------------------------------------------------------------------------
__global__ __launch_bounds__(128, 5) void conv_mma(const float* __restrict__ x,
                                                   const float* __restrict__ A) {
    extern __shared__ char sm[];
    __half* Xh = (__half*)(sm + XH_B);
    __half* Ah = (__half*)(sm + AH_B);
    float*  St = (float*)(sm + ST_B);

    const uint32_t smb = smem_u32(sm);
    const int tid  = threadIdx.x;
    const int warp = tid >> 5, lane = tid & 31;
    const int grp  = lane >> 2, tig = lane & 3;
    const int n    = blockIdx.x >> 6;            // 64 t-blocks per n
    const int t0   = (blockIdx.x & 63) * TB;

    St[tid] = 0.f;

    // --- A smem: [3*32][40] halves, zero-padded beyond 25x25 ---
    for (int i = tid; i < HH*32*32; i += 128) {
        int h = i >> 10, rem = i & 1023;
        int v = rem >> 5, u = rem & 31;
        float val = (v < VV && u < VV) ? A[(h*VV + v)*VV + u] : 0.f;
        Ah[(h*32 + v)*40 + u] = __float2half_rn(val);
    }
    // --- X pad: cols 32t+25..32t+31 zero, all 64 rows ---
    for (int i = tid; i < 64*56; i += 128) {
        int r = i / 56, k = i - r*56;
        int col = 32*(k/7) + 25 + (k%7);
        Xh[r*XS + col] = __float2half(0.f);
    }
    // --- X fill natural: Xh[c][32*(s/25) + s%25] from 200 contiguous floats/c ---
    {
        const float4* x4 = reinterpret_cast<const float4*>(x);
        for (int i = tid; i < CC*50; i += 128) {
            int c = i / 50, q = i - c*50;
            unsigned base = ((unsigned)(n*CC + c)*TT + t0)*VV;   // divisible by 4
            float4 v = x4[(base >> 2) + q];
            float vv[4] = {v.x, v.y, v.z, v.w};
            #pragma unroll
            for (int e = 0; e < 4; ++e) {
                int s = q*4 + e;
                int col = (s/25)*32 + (s - (s/25)*25);
                Xh[c*XS + col] = __float2half_rn(vv[e]);
            }
        }
    }
    __syncthreads();

    // ldmatrix address components
    const int q4 = lane >> 3, r8 = lane & 7;
    const int brow = lane & 7;
    const int bcol8 = (lane & 8) ? 8 : 0;
    const uint32_t xlane = (uint32_t)((r8 + ((q4 & 1) ? 8 : 0)) * XS + ((q4 & 2) ? 8 : 0)) * 2;

    const uint4* wbase = g_Wf + warp*4*32 + lane;

    float st1a = 0.f, st2a = 0.f, st1b = 0.f, st2b = 0.f;
    const int r0 = warp*16 + grp, r1 = r0 + 8;

    for (int t = 0; t < TB; ++t) {
        // ---- X b-fragments for this t (32 regs, hoisted across h) ----
        uint32_t xf[4][2][4];
        #pragma unroll
        for (int kk = 0; kk < 4; ++kk)
            #pragma unroll
            for (int jp = 0; jp < 2; ++jp) {
                uint32_t off = xlane + (uint32_t)((16*kk)*XS + 32*t + 16*jp) * 2;
                ldmx4t(xf[kk][jp][0], xf[kk][jp][1], xf[kk][jp][2], xf[kk][jp][3],
                       smb + XH_B + off);
            }

        float OUT[4][4];
        #pragma unroll
        for (int nv = 0; nv < 4; ++nv)
            #pragma unroll
            for (int e = 0; e < 4; ++e) OUT[nv][e] = 0.f;

        #pragma unroll
        for (int h = 0; h < HH; ++h) {
            // stage 1
            float Y[4][4];
            #pragma unroll
            for (int j = 0; j < 4; ++j)
                #pragma unroll
                for (int e = 0; e < 4; ++e) Y[j][e] = 0.f;

            #pragma unroll
            for (int kk = 0; kk < 4; ++kk) {
                uint4 wv = __ldg(wbase + (h*16 + kk)*32);
                uint32_t whf[4] = {wv.x, wv.y, wv.z, wv.w};
                #pragma unroll
                for (int j = 0; j < 4; ++j) {
                    int jp = j >> 1, ix = (j & 1) * 2;
                    mma16(Y[j], whf, xf[kk][jp][ix], xf[kk][jp][ix + 1]);
                }
            }

            // stage 2: B2 loaded per kp (same LDSM count, shorter liveness)
            #pragma unroll
            for (int kp = 0; kp < 2; ++kp) {
                uint32_t ah[4];
                #pragma unroll
                for (int i = 0; i < 4; ++i) {
                    const float* yp = Y[2*kp + (i >> 1)];
                    float p  = yp[(i & 1) ? 2 : 0];
                    float qv = yp[(i & 1) ? 3 : 1];
                    ah[i] = h2u(__floats2half2_rn(p, qv));
                }
                #pragma unroll
                for (int nv = 0; nv < 4; ++nv) {
                    uint32_t b0, b1;
                    uint32_t off = (uint32_t)(((h*32 + 8*nv + brow)*40) + kp*16 + bcol8) * 2;
                    ldmx2(b0, b1, smb + AH_B + off);
                    mma16(OUT[nv], ah, b0, b1);
                }
            }
        }

        // ---- branchless epilogue: aligned half2 stores into 64B rows ----
        unsigned rowA = ((unsigned)(n*CC + r0)*TT + t0 + t);
        unsigned rowB = ((unsigned)(n*CC + r1)*TT + t0 + t);
        #pragma unroll
        for (int nv = 0; nv < 4; ++nv) {
            int p2 = (8*nv + 2*tig) >> 1;       // half2 slot within row
            float a0 = OUT[nv][0], a1 = OUT[nv][1];
            float b0 = OUT[nv][2], b1 = OUT[nv][3];
            g_convP[rowA*16 + p2] = __floats2half2_rn(a0, a1);
            g_convP[rowB*16 + p2] = __floats2half2_rn(b0, b1);
            st1a += a0 + a1; st2a += a0*a0 + a1*a1;
            st1b += b0 + b1; st2b += b0*b0 + b1*b1;
        }
    }

    // --- stats: smem reduce, one global atomic per tid ---
    atomicAdd(&St[r0],      st1a);
    atomicAdd(&St[64 + r0], st2a);
    atomicAdd(&St[r1],      st1b);
    atomicAdd(&St[64 + r1], st2b);
    __syncthreads();
    atomicAdd(&g_stats[tid], St[tid]);
}

// ---------------------------------------------------------------------------
__global__ void stats_k(const float* __restrict__ gamma, const float* __restrict__ beta) {
    int o = threadIdx.x;
    if (o < CC) {
        const float inv = 1.f / (float)CNT_F;
        float mean = g_stats[o] * inv;
        float var  = g_stats[64 + o] * inv - mean*mean;
        float sc = gamma[o] * rsqrtf(var + 1e-5f);
        g_scale[o] = sc;
        g_shift[o] = beta[o] - mean*sc;
    }
}

// ---------------------------------------------------------------------------
// pass 2: out = relu(scale[c]*convP + shift[c] + x); convP rows padded to 32.
// ---------------------------------------------------------------------------
__global__ void bn_apply(const float4* __restrict__ xv, float4* __restrict__ ov) {
    const __half* ch = reinterpret_cast<const __half*>(g_convP);
    const int n4 = TOTAL / 4;
    int stride = gridDim.x * blockDim.x;
    for (int i = blockIdx.x * blockDim.x + threadIdx.x; i < n4; i += stride) {
        unsigned g = (unsigned)i * 4u;
        unsigned q = g / 25u;
        int v = (int)(g - q*25u);
        int c = (q >> 9) & 63;
        float s  = __ldg(&g_scale[c]);
        float sh = __ldg(&g_shift[c]);
        float4 b = xv[i];
        float f[4];
        #pragma unroll
        for (int e = 0; e < 4; ++e) {
            int ve = v + e;
            int w = (ve >= VV) ? 1 : 0;
            f[e] = __half2float(__ldg(ch + (q + w)*32u + (ve - VV*w)));
        }
        float4 r;
        r.x = fmaxf(fmaf(s, f[0], sh) + b.x, 0.f);
        r.y = fmaxf(fmaf(s, f[1], sh) + b.y, 0.f);
        r.z = fmaxf(fmaf(s, f[2], sh) + b.z, 0.f);
        r.w = fmaxf(fmaf(s, f[3], sh) + b.w, 0.f);
        ov[i] = r;
    }
}

// ---------------------------------------------------------------------------
extern "C" void kernel_launch(void* const* d_in, const int* in_sizes, int n_in,
                              void* d_out, int out_size) {
    const float* x     = (const float*)d_in[0];
    const float* A     = (const float*)d_in[1];
    const float* W     = (const float*)d_in[2];
    // d_in[3] = b : cancels exactly under training-mode BatchNorm -> unused
    const float* gamma = (const float*)d_in[4];
    const float* beta  = (const float*)d_in[5];
    float* out = (float*)d_out;

    cudaFuncSetAttribute(conv_mma, cudaFuncAttributeMaxDynamicSharedMemorySize, SM_BYTES);

    prep_k<<<48, 256>>>(W);
    conv_mma<<<NN*(TT/TB), 128, SM_BYTES>>>(x, A);
    stats_k<<<1, 64>>>(gamma, beta);
    bn_apply<<<4096, 256>>>(reinterpret_cast<const float4*>(x),
                            reinterpret_cast<float4*>(out));
}